// round 5
// baseline (speedup 1.0000x reference)
#include <cuda_runtime.h>
#include <cuda_bf16.h>
#include <cstdint>
#include <cstddef>

#define N_NODES 100000
#define M_PAD   100096            // 782 * 128
#define N_EDGES 3200000
#define DIM 512

// ---------------- scratch (device globals; no runtime allocation) ----------
__device__ float g_bufA[(size_t)M_PAD * DIM];   // GEMM outputs
__device__ float g_bufB[(size_t)M_PAD * DIM];   // h1 (spmm1 output)
__device__ __nv_bfloat16 g_w1thi[DIM * DIM];
__device__ __nv_bfloat16 g_w1tlo[DIM * DIM];
__device__ __nv_bfloat16 g_w2thi[DIM * DIM];
__device__ __nv_bfloat16 g_w2tlo[DIM * DIM];
__device__ int   g_row_ptr[N_NODES + 1];
__device__ int   g_counts[N_NODES];
__device__ int   g_srcs[N_EDGES];
__device__ float g_vals[N_EDGES];

// ---------------- PTX helpers ----------------------------------------------
__device__ __forceinline__ uint32_t smem_u32(const void* p) {
    uint32_t a;
    asm("{ .reg .u64 t; cvta.to.shared.u64 t, %1; cvt.u32.u64 %0, t; }" : "=r"(a) : "l"(p));
    return a;
}

#define CP_ASYNC16(smaddr, gptr) \
    asm volatile("cp.async.cg.shared.global [%0], [%1], 16;" :: "r"(smaddr), "l"(gptr))
#define CP_COMMIT() asm volatile("cp.async.commit_group;" ::: "memory")
#define CP_WAIT(N)  asm volatile("cp.async.wait_group %0;" :: "n"(N) : "memory")

#define LDSM4(R0, R1, R2, R3, addr) \
    asm volatile("ldmatrix.sync.aligned.m8n8.x4.shared.b16 {%0,%1,%2,%3}, [%4];" \
                 : "=r"(R0), "=r"(R1), "=r"(R2), "=r"(R3) : "r"(addr))

#define MMA16816(C, A, B0, B1) \
    asm volatile("mma.sync.aligned.m16n8k16.row.col.f32.bf16.bf16.f32 " \
                 "{%0,%1,%2,%3}, {%4,%5,%6,%7}, {%8,%9}, {%0,%1,%2,%3};" \
                 : "+f"((C)[0]), "+f"((C)[1]), "+f"((C)[2]), "+f"((C)[3]) \
                 : "r"((A)[0]), "r"((A)[1]), "r"((A)[2]), "r"((A)[3]), \
                   "r"(B0), "r"(B1))

#define STS128(addr, a, b, c, d) \
    asm volatile("st.shared.v4.b32 [%0], {%1,%2,%3,%4};" \
                 :: "r"(addr), "r"(a), "r"(b), "r"(c), "r"(d) : "memory")

// ---------------- CSR build -------------------------------------------------
__global__ void zero_counts_kernel() {
    int i = blockIdx.x * blockDim.x + threadIdx.x;
    if (i < N_NODES) g_counts[i] = 0;
}

__global__ void hist_kernel(const int* __restrict__ dst) {
    int e = blockIdx.x * blockDim.x + threadIdx.x;
    if (e < N_EDGES) atomicAdd(&g_counts[__ldcs(dst + e)], 1);
}

__global__ __launch_bounds__(1024) void scan_kernel() {
    __shared__ int partials[1024];
    int tid = threadIdx.x;
    const int CHUNK = (N_NODES + 1023) / 1024;
    int b = tid * CHUNK;
    int e = b + CHUNK; if (e > N_NODES) e = N_NODES;
    if (b > N_NODES) b = N_NODES;
    int sum = 0;
    for (int i = b; i < e; i++) sum += g_counts[i];
    partials[tid] = sum;
    __syncthreads();
    for (int off = 1; off < 1024; off <<= 1) {
        int t = (tid >= off) ? partials[tid - off] : 0;
        __syncthreads();
        partials[tid] += t;
        __syncthreads();
    }
    int run = partials[tid] - sum;
    for (int i = b; i < e; i++) {
        g_row_ptr[i] = run;
        run += g_counts[i];
        g_counts[i] = 0;
    }
    if (tid == 1023) g_row_ptr[N_NODES] = partials[1023];
}

__global__ void scatter_kernel(const int* __restrict__ src, const int* __restrict__ dst,
                               const float* __restrict__ val) {
    int e = blockIdx.x * blockDim.x + threadIdx.x;
    if (e >= N_EDGES) return;
    int d = __ldcs(dst + e);
    int pos = g_row_ptr[d] + atomicAdd(&g_counts[d], 1);
    g_srcs[pos] = __ldcs(src + e);
    g_vals[pos] = __ldcs(val + e);
}

// ---------------- weight prep: W[k][n] -> Wt[n][k], split hi/lo --------------
__global__ void wsplit_kernel(const float* __restrict__ W,
                              __nv_bfloat16* __restrict__ hi, __nv_bfloat16* __restrict__ lo) {
    int idx = blockIdx.x * blockDim.x + threadIdx.x;
    if (idx >= DIM * DIM) return;
    int k = idx >> 9, n = idx & 511;
    float v = W[idx];
    __nv_bfloat16 h = __float2bfloat16(v);
    __nv_bfloat16 l = __float2bfloat16(v - __bfloat162float(h));
    hi[n * DIM + k] = h;
    lo[n * DIM + k] = l;
}

// ---------------- HMMA bf16-split GEMM, fp32 A fused split -------------------
// C[.,512] = A(fp32) @ Wt^T + bias ; A split to bf16 hi/lo in-kernel.
// CTA 128x128, 8 warps (warp 64x32), K-chunk 32, double-buffered smem,
// A via LDG+convert+STS with register prefetch, B via cp.async.
#define BK 32
#define ROWB 80
#define OFF_AHI 0
#define OFF_ALO 10240
#define OFF_BHI 20480
#define OFF_BLO 30720
#define STAGE_BYTES 40960
#define GEMM_SMEM (2 * STAGE_BYTES)
#define NIT (DIM / BK)               // 16

struct AFrag { float4 v[4]; };       // 16 floats: row tid>>1, cols (tid&1)*16..+15

__device__ __forceinline__ void ldA(AFrag& f, const float* __restrict__ A,
                                    int m0, int k0, int tid, int Mlimit) {
    int r = tid >> 1;
    int c0 = (tid & 1) * 16;
    int gm = m0 + r;
    if (gm < Mlimit) {
        const float4* p = (const float4*)(A + (size_t)gm * DIM + k0 + c0);
        f.v[0] = p[0]; f.v[1] = p[1]; f.v[2] = p[2]; f.v[3] = p[3];
    } else {
        f.v[0] = f.v[1] = f.v[2] = f.v[3] = make_float4(0.f, 0.f, 0.f, 0.f);
    }
}

__device__ __forceinline__ void stA(uint32_t stage_base, const AFrag& f, int tid) {
    int r = tid >> 1;
    int c0 = (tid & 1) * 16;
    const float* x = (const float*)&f;
    uint32_t hi[8], lo[8];
#pragma unroll
    for (int j = 0; j < 8; j++) {
        float a = x[2 * j], b = x[2 * j + 1];
        __nv_bfloat16 ha = __float2bfloat16(a), hb = __float2bfloat16(b);
        __nv_bfloat16 la = __float2bfloat16(a - __bfloat162float(ha));
        __nv_bfloat16 lb = __float2bfloat16(b - __bfloat162float(hb));
        hi[j] = (uint32_t)__bfloat16_as_ushort(ha) | ((uint32_t)__bfloat16_as_ushort(hb) << 16);
        lo[j] = (uint32_t)__bfloat16_as_ushort(la) | ((uint32_t)__bfloat16_as_ushort(lb) << 16);
    }
    uint32_t off = (uint32_t)r * ROWB + (uint32_t)c0 * 2;
    STS128(stage_base + OFF_AHI + off,      hi[0], hi[1], hi[2], hi[3]);
    STS128(stage_base + OFF_AHI + off + 16, hi[4], hi[5], hi[6], hi[7]);
    STS128(stage_base + OFF_ALO + off,      lo[0], lo[1], lo[2], lo[3]);
    STS128(stage_base + OFF_ALO + off + 16, lo[4], lo[5], lo[6], lo[7]);
}

__device__ __forceinline__ void ldB_async(uint32_t stage_base,
                                          const __nv_bfloat16* __restrict__ Bhi,
                                          const __nv_bfloat16* __restrict__ Blo,
                                          int n0, int k0, int tid) {
#pragma unroll
    for (int i = tid; i < 512; i += 256) {
        int r = i >> 2, s = i & 3;
        uint32_t so = (uint32_t)r * ROWB + (uint32_t)s * 16u;
        const char* gc = (const char*)(Bhi + (size_t)(n0 + r) * DIM + k0) + s * 16;
        const char* gd = (const char*)(Blo + (size_t)(n0 + r) * DIM + k0) + s * 16;
        CP_ASYNC16(stage_base + OFF_BHI + so, gc);
        CP_ASYNC16(stage_base + OFF_BLO + so, gd);
    }
}

__global__ __launch_bounds__(256, 2) void gemm_fused_kernel(
    const float* __restrict__ A,
    const __nv_bfloat16* __restrict__ Bhi, const __nv_bfloat16* __restrict__ Blo,
    const float* __restrict__ bias, float* __restrict__ C, int Mlimit)
{
    extern __shared__ char sm[];
    const uint32_t sbase = smem_u32(sm);
    const int tid  = threadIdx.x;
    const int warp = tid >> 5;
    const int lane = tid & 31;
    const int wm = warp & 1;
    const int wn = warp >> 1;
    const int n0 = blockIdx.x * 128;      // n fastest -> wave shares A rows
    const int m0 = blockIdx.y * 128;

    float acc[4][4][4];
#pragma unroll
    for (int a = 0; a < 4; a++)
#pragma unroll
        for (int b = 0; b < 4; b++)
#pragma unroll
            for (int c = 0; c < 4; c++) acc[a][b][c] = 0.f;

    const int a_row = lane & 15;
    const int a_koff = (lane >> 4) * 8;
    const int b_g = lane >> 3;
    const int b_nloc = ((b_g >> 1) << 3) + (lane & 7);
    const int b_koff = (b_g & 1) * 8;

    AFrag afrag;
    ldA(afrag, A, m0, 0, tid, Mlimit);
    ldB_async(sbase, Bhi, Blo, n0, 0, tid);
    CP_COMMIT();

    for (int it = 0; it < NIT; ++it) {
        const uint32_t st = sbase + (uint32_t)(it & 1) * STAGE_BYTES;
        if (it + 1 < NIT) {
            ldB_async(sbase + (uint32_t)((it + 1) & 1) * STAGE_BYTES, Bhi, Blo,
                      n0, (it + 1) * BK, tid);
            CP_COMMIT();
            CP_WAIT(1);
        } else {
            CP_WAIT(0);
        }
        stA(st, afrag, tid);
        __syncthreads();
        if (it + 1 < NIT) ldA(afrag, A, m0, (it + 1) * BK, tid, Mlimit);

#pragma unroll
        for (int kk = 0; kk < 2; ++kk) {
            const int k16 = kk * 16;
            uint32_t ahi[4][4], alo[4][4];
#pragma unroll
            for (int mi = 0; mi < 4; ++mi) {
                uint32_t ra = (uint32_t)(wm * 64 + mi * 16 + a_row) * ROWB
                            + (uint32_t)(k16 + a_koff) * 2;
                LDSM4(ahi[mi][0], ahi[mi][1], ahi[mi][2], ahi[mi][3], st + OFF_AHI + ra);
                LDSM4(alo[mi][0], alo[mi][1], alo[mi][2], alo[mi][3], st + OFF_ALO + ra);
            }
            uint32_t bhi[2][4], blo[2][4];
#pragma unroll
            for (int nb = 0; nb < 2; ++nb) {
                uint32_t rb = (uint32_t)(wn * 32 + nb * 16 + b_nloc) * ROWB
                            + (uint32_t)(k16 + b_koff) * 2;
                LDSM4(bhi[nb][0], bhi[nb][1], bhi[nb][2], bhi[nb][3], st + OFF_BHI + rb);
                LDSM4(blo[nb][0], blo[nb][1], blo[nb][2], blo[nb][3], st + OFF_BLO + rb);
            }
#pragma unroll
            for (int mi = 0; mi < 4; ++mi) {
#pragma unroll
                for (int j = 0; j < 4; ++j) {
                    const int nb = j >> 1, blk = j & 1;
                    MMA16816(acc[mi][j], ahi[mi], bhi[nb][blk * 2], bhi[nb][blk * 2 + 1]);
                    MMA16816(acc[mi][j], ahi[mi], blo[nb][blk * 2], blo[nb][blk * 2 + 1]);
                    MMA16816(acc[mi][j], alo[mi], bhi[nb][blk * 2], bhi[nb][blk * 2 + 1]);
                }
            }
        }
        __syncthreads();
    }

    // epilogue: bias add + store fp32 (streaming)
#pragma unroll
    for (int mi = 0; mi < 4; ++mi) {
        int row = m0 + wm * 64 + mi * 16 + (lane >> 2);
#pragma unroll
        for (int j = 0; j < 4; ++j) {
            int col = n0 + wn * 32 + j * 8 + (lane & 3) * 2;
            float b0 = bias[col], b1 = bias[col + 1];
            float2 v0 = make_float2(acc[mi][j][0] + b0, acc[mi][j][1] + b1);
            float2 v1 = make_float2(acc[mi][j][2] + b0, acc[mi][j][3] + b1);
            __stcs((float2*)(C + (size_t)row * DIM + col), v0);
            __stcs((float2*)(C + (size_t)(row + 8) * DIM + col), v1);
        }
    }
}

// ---------------- SpMM (CSR by dst), one warp per row, fused ReLU ------------
__device__ __forceinline__ void fma4(float4& acc, float v, const float4& a) {
    acc.x += v * a.x; acc.y += v * a.y; acc.z += v * a.z; acc.w += v * a.w;
}
__device__ __forceinline__ float4 relu4(float4 a) {
    a.x = fmaxf(a.x, 0.f); a.y = fmaxf(a.y, 0.f);
    a.z = fmaxf(a.z, 0.f); a.w = fmaxf(a.w, 0.f);
    return a;
}

__global__ __launch_bounds__(256) void spmm_f32_kernel(const float* __restrict__ H,
                                                       float* __restrict__ out) {
    int row  = (blockIdx.x * blockDim.x + threadIdx.x) >> 5;
    int lane = threadIdx.x & 31;
    if (row >= N_NODES) return;
    int beg = g_row_ptr[row];
    int end = g_row_ptr[row + 1];
    float4 a0 = make_float4(0.f, 0.f, 0.f, 0.f), a1 = a0, a2 = a0, a3 = a0;
    for (int base = beg; base < end; base += 32) {
        int cnt = end - base; if (cnt > 32) cnt = 32;
        int s = 0; float v = 0.f;
        if (lane < cnt) { s = __ldcs(g_srcs + base + lane); v = __ldcs(g_vals + base + lane); }
        for (int k = 0; k < cnt; k++) {
            int   sk = __shfl_sync(0xffffffffu, s, k);
            float vk = __shfl_sync(0xffffffffu, v, k);
            const float4* hp = (const float4*)(H + (size_t)sk * DIM);
            fma4(a0, vk, hp[lane]);
            fma4(a1, vk, hp[lane + 32]);
            fma4(a2, vk, hp[lane + 64]);
            fma4(a3, vk, hp[lane + 96]);
        }
    }
    float4* op = (float4*)(out + (size_t)row * DIM);
    __stcs(op + lane,      relu4(a0));
    __stcs(op + lane + 32, relu4(a1));
    __stcs(op + lane + 64, relu4(a2));
    __stcs(op + lane + 96, relu4(a3));
}

// ---------------- launcher ----------------------------------------------------
extern "C" void kernel_launch(void* const* d_in, const int* in_sizes, int n_in,
                              void* d_out, int out_size)
{
    const float* x    = (const float*)d_in[0];
    const int*   asrc = (const int*)  d_in[1];
    const int*   adst = (const int*)  d_in[2];
    const float* aval = (const float*)d_in[3];
    const float* W1   = (const float*)d_in[4];
    const float* b1   = (const float*)d_in[5];
    const float* W2   = (const float*)d_in[6];
    const float* b2   = (const float*)d_in[7];
    float* out = (float*)d_out;

    float *bufA, *bufB;
    __nv_bfloat16 *w1thi, *w1tlo, *w2thi, *w2tlo;
    cudaGetSymbolAddress((void**)&bufA,  g_bufA);
    cudaGetSymbolAddress((void**)&bufB,  g_bufB);
    cudaGetSymbolAddress((void**)&w1thi, g_w1thi);
    cudaGetSymbolAddress((void**)&w1tlo, g_w1tlo);
    cudaGetSymbolAddress((void**)&w2thi, g_w2thi);
    cudaGetSymbolAddress((void**)&w2tlo, g_w2tlo);

    cudaFuncSetAttribute(gemm_fused_kernel, cudaFuncAttributeMaxDynamicSharedMemorySize,
                         GEMM_SMEM);

    dim3 ggrid(DIM / 128, M_PAD / 128);   // (4 n-blocks fastest, 782 m-blocks)

    // prep + GEMM1 (gemm1 at profiled slot idx 3)
    wsplit_kernel<<<(DIM * DIM + 255) / 256, 256>>>(W1, w1thi, w1tlo);
    wsplit_kernel<<<(DIM * DIM + 255) / 256, 256>>>(W2, w2thi, w2tlo);
    zero_counts_kernel<<<(N_NODES + 255) / 256, 256>>>();
    gemm_fused_kernel<<<ggrid, 256, GEMM_SMEM>>>(x, w1thi, w1tlo, b1, bufA, N_NODES);

    // CSR build
    hist_kernel<<<(N_EDGES + 255) / 256, 256>>>(adst);
    scan_kernel<<<1, 1024>>>();
    scatter_kernel<<<(N_EDGES + 255) / 256, 256>>>(asrc, adst, aval);

    // Layer 1 aggregate -> bufB
    spmm_f32_kernel<<<(N_NODES + 7) / 8, 256>>>(bufA, bufB);

    // Layer 2
    gemm_fused_kernel<<<ggrid, 256, GEMM_SMEM>>>(bufB, w2thi, w2tlo, b2, bufA, N_NODES);
    spmm_f32_kernel<<<(N_NODES + 7) / 8, 256>>>(bufA, out);
}